// round 17
// baseline (speedup 1.0000x reference)
#include <cuda_runtime.h>
#include <cstdint>

// Problem constants (fixed by the reference).
#define IMAGE_TOKEN_ID 31999
#define B_DIM 4
#define L_DIM 1024
#define D_DIM 2048
#define NUM_VIS 576
#define NEW_LEN (L_DIM - 1 + NUM_VIS)      // 1599
#define NROWS  (B_DIM * NEW_LEN)           // 6396

#define GRID_BLOCKS 1216                   // 152 SMs x 8 CTAs -> one wave

// Store with L2 evict_last via createpolicy + cache_hint (works on v4.f32,
// unlike the static .L2::evict_last qualifier which ptxas restricts to
// 256-bit ops). Goal: output lines stay L2-resident across graph replays so
// dirty write-back to DRAM (the measured 52MB/replay DRAM traffic) vanishes.
__device__ __forceinline__ void stg_el(float4* p, float4 v, uint64_t pol) {
    asm volatile("st.global.L2::cache_hint.v4.f32 [%0], {%1,%2,%3,%4}, %5;"
                 :: "l"(p), "f"(v.x), "f"(v.y), "f"(v.z), "f"(v.w), "l"(pol)
                 : "memory");
}

// ---------------------------------------------------------------------------
// Single fused persistent kernel (R15 structure, stores now policy-hinted).
// Phase 1: every block scans all 4096 input_ids (16 KB; L1/L2-resident) to
//          find the 4 image-token positions.
// Phase 2: grid-stride over 6396 output rows; one 8 KB row per iteration.
// ---------------------------------------------------------------------------
__global__ __launch_bounds__(256, 8)
void fused_merge_kernel(const int* __restrict__ input_ids,
                        const float4* __restrict__ visual,   // [B, NUM_VIS, D/4]
                        const float4* __restrict__ embed,    // [32768, D/4]
                        float4* __restrict__ out,            // [B, NEW_LEN, D/4]
                        float* __restrict__ out_flat,
                        int write_pos)
{
    __shared__ int s_ip[B_DIM];
    const int t = threadIdx.x;

    uint64_t pol;
    asm("createpolicy.fractional.L2::evict_last.b64 %0, 1.0;" : "=l"(pol));

    // Phase 1: scan input_ids. 4096 ints = 1024 int4; 256 threads x 4 int4.
    const int4* ids4 = (const int4*)input_ids;
    #pragma unroll
    for (int k = 0; k < 4; k++) {
        const int idx4 = t + k * 256;          // 0..1023
        const int4 v = __ldg(ids4 + idx4);
        const int base = idx4 * 4;
        if (v.x == IMAGE_TOKEN_ID) s_ip[ base      / L_DIM] =  base      % L_DIM;
        if (v.y == IMAGE_TOKEN_ID) s_ip[(base + 1) / L_DIM] = (base + 1) % L_DIM;
        if (v.z == IMAGE_TOKEN_ID) s_ip[(base + 2) / L_DIM] = (base + 2) % L_DIM;
        if (v.w == IMAGE_TOKEN_ID) s_ip[(base + 3) / L_DIM] = (base + 3) % L_DIM;
    }
    __syncthreads();

    // Phase 2: persistent grid-stride over output rows.
    for (int row = blockIdx.x; row < NROWS; row += GRID_BLOCKS) {
        const int b  = row / NEW_LEN;
        const int j  = row - b * NEW_LEN;
        const int ip = s_ip[b];

        const float4* src;
        if (j >= ip && j < ip + NUM_VIS) {
            src = visual + ((size_t)b * NUM_VIS + (size_t)(j - ip)) * (D_DIM / 4);
        } else {
            const int l   = (j < ip) ? j : j - (NUM_VIS - 1);
            const int tok = __ldg(input_ids + b * L_DIM + l);   // L1/L2-hit
            src = embed + (size_t)tok * (D_DIM / 4);
        }

        const float4 v0 = __ldg(src + t);
        const float4 v1 = __ldg(src + t + 256);
        float4* dst = out + (size_t)row * (D_DIM / 4);
        stg_el(dst + t,       v0, pol);
        stg_el(dst + t + 256, v1, pol);

        if (write_pos && t == 0) {
            out_flat[(size_t)NROWS * D_DIM + row] = (float)j;
        }
    }
}

// ---------------------------------------------------------------------------
// Launch contract
// inputs (metadata order): input_ids [B,L] int32, visual_tokens [B,NUM_VIS,D]
// float32, embed_table [32768,D] float32.
// output: merged [B,NEW_LEN,D] float32 (+ optionally position_ids appended).
// ---------------------------------------------------------------------------
extern "C" void kernel_launch(void* const* d_in, const int* in_sizes, int n_in,
                              void* d_out, int out_size)
{
    const int*    input_ids = (const int*)   d_in[0];
    const float4* visual    = (const float4*)d_in[1];
    const float4* embed     = (const float4*)d_in[2];

    float4* out      = (float4*)d_out;
    float*  out_flat = (float*) d_out;

    const long long merged_elems = (long long)NROWS * D_DIM;
    const int write_pos = (out_size > merged_elems) ? 1 : 0;

    fused_merge_kernel<<<GRID_BLOCKS, 256>>>(input_ids, visual, embed,
                                             out, out_flat, write_pos);
}